// round 12
// baseline (speedup 1.0000x reference)
#include <cuda_runtime.h>
#include <cstdint>

// Grayscale erosion, 5x5 non-flat SE, 'same' padding with +inf.
// out[p,y,x] = min_{i,j in 0..4} img[p, y+i-2, x+j-2] - filt[i,j]
//
// fp32 scalar floor: 25 FADD + 24 FMNMX per pixel (issue-cap == alu-pipe cap
// ~= 140us). This version removes the fill-latency stalls of the one-shot
// tile kernel: each block sweeps 4 vertical tiles with double-buffered smem
// and register-staged prefetch (LDG before compute, STS after), 1 sync/iter.

#define WIDTH   1024
#define HEIGHT  1024
#define TILE_X  128
#define TILE_Y  32
#define ITERS   4
#define YSPAN   (TILE_Y * ITERS)     // 128
#define XT      (WIDTH / TILE_X)     // 8
#define YT      (HEIGHT / YSPAN)     // 8
#define RX      4
#define RY      4
#define BDX     32
#define BDY     8
#define NTHR    (BDX * BDY)          // 256
// smem tile: gmem cols [x0-4, x0+131] (16B-aligned vec loads), rows [y0-2, y0+33]
#define SW      136
#define SH      36
#define SW4     (SW / 4)             // 34 float4 per row
#define NV4     (SH * SW4)           // 1224 float4 per tile
#define FINF    __int_as_float(0x7f800000)

__global__ __launch_bounds__(NTHR)
void erosion5x5_kernel(const float* __restrict__ img,
                       const float* __restrict__ filt,
                       float* __restrict__ out)
{
    __shared__ __align__(16) float s_tile[2][SH][SW];
    __shared__ float s_nf[25];

    const int tx  = threadIdx.x;            // 0..31
    const int ty  = threadIdx.y;            // 0..7
    const int tid = ty * BDX + tx;          // 0..255

    const int x0    = blockIdx.x * TILE_X;
    const int ybase = blockIdx.y * YSPAN;
    const size_t plane = (size_t)blockIdx.z * (size_t)(WIDTH * HEIGHT);
    const float* __restrict__ p = img + plane;
    float* __restrict__ o       = out + plane;

    const bool xInterior = (x0 >= 4) && (x0 + SW - 4 <= WIDTH);

    // negated filter (min identity preserved under +)
    if (tid < 25) s_nf[tid] = -filt[tid];

    // ---------------- fill helpers ----------------
    auto fill_fast = [&](int buf, int y0) {
        const float4* __restrict__ g =
            reinterpret_cast<const float4*>(p + (size_t)(y0 - 2) * WIDTH + (x0 - 4));
        float4* __restrict__ s = reinterpret_cast<float4*>(&s_tile[buf][0][0]);
        #pragma unroll
        for (int k = 0; k < 5; ++k) {
            int q = tid + k * NTHR;
            if (q < NV4) {
                int r  = q / SW4;
                int c4 = q - r * SW4;
                s[q] = g[(size_t)r * (WIDTH / 4) + c4];
            }
        }
    };
    auto fill_guarded = [&](int buf, int y0) {
        for (int idx = tid; idx < SH * SW; idx += NTHR) {
            int r  = idx / SW;
            int c  = idx - r * SW;
            int gr = y0 - 2 + r;
            int gc = x0 - 4 + c;
            float v = FINF;
            if (gr >= 0 && gr < HEIGHT && gc >= 0 && gc < WIDTH)
                v = p[(size_t)gr * WIDTH + gc];
            s_tile[buf][r][c] = v;
        }
    };
    auto fast_ok = [&](int y0) {
        return xInterior && (y0 >= 2) && (y0 + SH - 2 <= HEIGHT);
    };

    // initial fill of buffer 0
    if (fast_ok(ybase)) fill_fast(0, ybase);
    else                fill_guarded(0, ybase);
    __syncthreads();

    // filter into registers (LDS broadcast)
    float nf[25];
    #pragma unroll
    for (int i = 0; i < 25; ++i) nf[i] = s_nf[i];

    const int srow0 = ty * RY;
    const int scol0 = tx * RX;

    for (int t = 0; t < ITERS; ++t) {
        const int  cur   = t & 1;
        const int  y0    = ybase + t * TILE_Y;
        const bool last  = (t == ITERS - 1);
        const int  y0n   = y0 + TILE_Y;
        const bool fastN = !last && fast_ok(y0n);

        // ---- register-staged prefetch of next tile (hidden under compute) ----
        float4 pre[5];
        if (fastN) {
            const float4* __restrict__ g =
                reinterpret_cast<const float4*>(p + (size_t)(y0n - 2) * WIDTH + (x0 - 4));
            #pragma unroll
            for (int k = 0; k < 5; ++k) {
                int q = tid + k * NTHR;
                if (q < NV4) {
                    int r  = q / SW4;
                    int c4 = q - r * SW4;
                    pre[k] = g[(size_t)r * (WIDTH / 4) + c4];
                }
            }
        }

        // ---- compute 4x4 outputs per thread ----
        float acc[RY][RX];
        #pragma unroll
        for (int i = 0; i < RY + 4; ++i) {
            const float4* rowp =
                reinterpret_cast<const float4*>(&s_tile[cur][srow0 + i][scol0]);
            float4 a = rowp[0], b = rowp[1], d = rowp[2];
            float v[12] = { a.x, a.y, a.z, a.w,
                            b.x, b.y, b.z, b.w,
                            d.x, d.y, d.z, d.w };
            #pragma unroll
            for (int r = 0; r < RY; ++r) {
                const int fi = i - r;            // filter row hitting output row r
                if (fi < 0 || fi > 4) continue;  // compile-time DCE
                #pragma unroll
                for (int c = 0; c < RX; ++c) {
                    #pragma unroll
                    for (int fc = 0; fc < 5; ++fc) {
                        float cand = v[c + fc + 2] + nf[fi * 5 + fc];
                        if (fi == 0 && fc == 0) acc[r][c] = cand;  // first touch
                        else                    acc[r][c] = fminf(acc[r][c], cand);
                    }
                }
            }
        }

        // ---- store 4x4 block ----
        const int oy = y0 + ty * RY;
        const int ox = x0 + tx * RX;
        #pragma unroll
        for (int r = 0; r < RY; ++r) {
            float4 w = make_float4(acc[r][0], acc[r][1], acc[r][2], acc[r][3]);
            *reinterpret_cast<float4*>(o + (size_t)(oy + r) * WIDTH + ox) = w;
        }

        // ---- commit next tile to the other buffer ----
        if (!last) {
            if (fastN) {
                float4* __restrict__ s =
                    reinterpret_cast<float4*>(&s_tile[cur ^ 1][0][0]);
                #pragma unroll
                for (int k = 0; k < 5; ++k) {
                    int q = tid + k * NTHR;
                    if (q < NV4) s[q] = pre[k];
                }
            } else {
                fill_guarded(cur ^ 1, y0n);
            }
        }
        __syncthreads();
    }
}

extern "C" void kernel_launch(void* const* d_in, const int* in_sizes, int n_in,
                              void* d_out, int out_size)
{
    const float* img  = (const float*)d_in[0];
    const float* filt = (const float*)d_in[1];
    float* out        = (float*)d_out;

    const int planes = in_sizes[0] / (WIDTH * HEIGHT);   // 32*3 = 96

    dim3 block(BDX, BDY);
    dim3 grid(XT, YT, planes);
    erosion5x5_kernel<<<grid, block>>>(img, filt, out);
}

// round 16
// speedup vs baseline: 1.0017x; 1.0017x over previous
#include <cuda_runtime.h>
#include <cstdint>

// Grayscale erosion, 5x5 non-flat SE, 'same' padding with +inf.
// out[p,y,x] = min_{i,j in 0..4} img[p, y+i-2, x+j-2] - filt[i,j]
//
// fp32 scalar floor: 25 FADD + 24 FMNMX per pixel (issue-cap == alu-pipe cap
// ~= 140us). This version removes the fill-latency stalls of the one-shot
// tile kernel: each block sweeps 4 vertical tiles with double-buffered smem
// and register-staged prefetch (LDG before compute, STS after), 1 sync/iter.

#define WIDTH   1024
#define HEIGHT  1024
#define TILE_X  128
#define TILE_Y  32
#define ITERS   4
#define YSPAN   (TILE_Y * ITERS)     // 128
#define XT      (WIDTH / TILE_X)     // 8
#define YT      (HEIGHT / YSPAN)     // 8
#define RX      4
#define RY      4
#define BDX     32
#define BDY     8
#define NTHR    (BDX * BDY)          // 256
// smem tile: gmem cols [x0-4, x0+131] (16B-aligned vec loads), rows [y0-2, y0+33]
#define SW      136
#define SH      36
#define SW4     (SW / 4)             // 34 float4 per row
#define NV4     (SH * SW4)           // 1224 float4 per tile
#define FINF    __int_as_float(0x7f800000)

__global__ __launch_bounds__(NTHR)
void erosion5x5_kernel(const float* __restrict__ img,
                       const float* __restrict__ filt,
                       float* __restrict__ out)
{
    __shared__ __align__(16) float s_tile[2][SH][SW];
    __shared__ float s_nf[25];

    const int tx  = threadIdx.x;            // 0..31
    const int ty  = threadIdx.y;            // 0..7
    const int tid = ty * BDX + tx;          // 0..255

    const int x0    = blockIdx.x * TILE_X;
    const int ybase = blockIdx.y * YSPAN;
    const size_t plane = (size_t)blockIdx.z * (size_t)(WIDTH * HEIGHT);
    const float* __restrict__ p = img + plane;
    float* __restrict__ o       = out + plane;

    const bool xInterior = (x0 >= 4) && (x0 + SW - 4 <= WIDTH);

    // negated filter (min identity preserved under +)
    if (tid < 25) s_nf[tid] = -filt[tid];

    // ---------------- fill helpers ----------------
    auto fill_fast = [&](int buf, int y0) {
        const float4* __restrict__ g =
            reinterpret_cast<const float4*>(p + (size_t)(y0 - 2) * WIDTH + (x0 - 4));
        float4* __restrict__ s = reinterpret_cast<float4*>(&s_tile[buf][0][0]);
        #pragma unroll
        for (int k = 0; k < 5; ++k) {
            int q = tid + k * NTHR;
            if (q < NV4) {
                int r  = q / SW4;
                int c4 = q - r * SW4;
                s[q] = g[(size_t)r * (WIDTH / 4) + c4];
            }
        }
    };
    auto fill_guarded = [&](int buf, int y0) {
        for (int idx = tid; idx < SH * SW; idx += NTHR) {
            int r  = idx / SW;
            int c  = idx - r * SW;
            int gr = y0 - 2 + r;
            int gc = x0 - 4 + c;
            float v = FINF;
            if (gr >= 0 && gr < HEIGHT && gc >= 0 && gc < WIDTH)
                v = p[(size_t)gr * WIDTH + gc];
            s_tile[buf][r][c] = v;
        }
    };
    auto fast_ok = [&](int y0) {
        return xInterior && (y0 >= 2) && (y0 + SH - 2 <= HEIGHT);
    };

    // initial fill of buffer 0
    if (fast_ok(ybase)) fill_fast(0, ybase);
    else                fill_guarded(0, ybase);
    __syncthreads();

    // filter into registers (LDS broadcast)
    float nf[25];
    #pragma unroll
    for (int i = 0; i < 25; ++i) nf[i] = s_nf[i];

    const int srow0 = ty * RY;
    const int scol0 = tx * RX;

    for (int t = 0; t < ITERS; ++t) {
        const int  cur   = t & 1;
        const int  y0    = ybase + t * TILE_Y;
        const bool last  = (t == ITERS - 1);
        const int  y0n   = y0 + TILE_Y;
        const bool fastN = !last && fast_ok(y0n);

        // ---- register-staged prefetch of next tile (hidden under compute) ----
        float4 pre[5];
        if (fastN) {
            const float4* __restrict__ g =
                reinterpret_cast<const float4*>(p + (size_t)(y0n - 2) * WIDTH + (x0 - 4));
            #pragma unroll
            for (int k = 0; k < 5; ++k) {
                int q = tid + k * NTHR;
                if (q < NV4) {
                    int r  = q / SW4;
                    int c4 = q - r * SW4;
                    pre[k] = g[(size_t)r * (WIDTH / 4) + c4];
                }
            }
        }

        // ---- compute 4x4 outputs per thread ----
        float acc[RY][RX];
        #pragma unroll
        for (int i = 0; i < RY + 4; ++i) {
            const float4* rowp =
                reinterpret_cast<const float4*>(&s_tile[cur][srow0 + i][scol0]);
            float4 a = rowp[0], b = rowp[1], d = rowp[2];
            float v[12] = { a.x, a.y, a.z, a.w,
                            b.x, b.y, b.z, b.w,
                            d.x, d.y, d.z, d.w };
            #pragma unroll
            for (int r = 0; r < RY; ++r) {
                const int fi = i - r;            // filter row hitting output row r
                if (fi < 0 || fi > 4) continue;  // compile-time DCE
                #pragma unroll
                for (int c = 0; c < RX; ++c) {
                    #pragma unroll
                    for (int fc = 0; fc < 5; ++fc) {
                        float cand = v[c + fc + 2] + nf[fi * 5 + fc];
                        if (fi == 0 && fc == 0) acc[r][c] = cand;  // first touch
                        else                    acc[r][c] = fminf(acc[r][c], cand);
                    }
                }
            }
        }

        // ---- store 4x4 block ----
        const int oy = y0 + ty * RY;
        const int ox = x0 + tx * RX;
        #pragma unroll
        for (int r = 0; r < RY; ++r) {
            float4 w = make_float4(acc[r][0], acc[r][1], acc[r][2], acc[r][3]);
            *reinterpret_cast<float4*>(o + (size_t)(oy + r) * WIDTH + ox) = w;
        }

        // ---- commit next tile to the other buffer ----
        if (!last) {
            if (fastN) {
                float4* __restrict__ s =
                    reinterpret_cast<float4*>(&s_tile[cur ^ 1][0][0]);
                #pragma unroll
                for (int k = 0; k < 5; ++k) {
                    int q = tid + k * NTHR;
                    if (q < NV4) s[q] = pre[k];
                }
            } else {
                fill_guarded(cur ^ 1, y0n);
            }
        }
        __syncthreads();
    }
}

extern "C" void kernel_launch(void* const* d_in, const int* in_sizes, int n_in,
                              void* d_out, int out_size)
{
    const float* img  = (const float*)d_in[0];
    const float* filt = (const float*)d_in[1];
    float* out        = (float*)d_out;

    const int planes = in_sizes[0] / (WIDTH * HEIGHT);   // 32*3 = 96

    dim3 block(BDX, BDY);
    dim3 grid(XT, YT, planes);
    erosion5x5_kernel<<<grid, block>>>(img, filt, out);
}

// round 17
// speedup vs baseline: 1.2519x; 1.2497x over previous
#include <cuda_runtime.h>
#include <cuda_fp16.h>
#include <cstdint>

// Grayscale erosion, 5x5 non-flat SE, 'same' padding with +inf.
// out[p,y,x] = min_{i,j} img[p, y+i-2, x+j-2] - filt[i,j]
//
// fp16x2 packed inner loop: HADD2 + HMNMX2 process two output columns per
// instruction (12.5 adds + 12 mins per pixel vs 49 scalar fp32 ops).
// gmem I/O stays fp32 (traffic already at the ~805MB minimum); the smem tile
// is fp16. Odd-offset half2 pairs built with PRMT, shared across output rows.

#define WIDTH   1024
#define HEIGHT  1024
#define TILE_X  128
#define TILE_Y  64
#define BDX     16
#define BDY     16
#define NTHR    (BDX * BDY)      // 256
#define RX      8                // output cols per thread (4 half2 pairs)
#define RY      4                // output rows per thread
#define SH      (TILE_Y + 4)     // 68 smem rows
#define SWH     144              // halfs per smem row; local L = gx - (x0-6)
#define FINF    __int_as_float(0x7f800000)

union U32H2 { uint32_t u; __half2 h; };
static __device__ __forceinline__ __half2 u2h2(uint32_t u) { U32H2 t; t.u = u; return t.h; }

__global__ __launch_bounds__(NTHR)
void erosion5x5_h2_kernel(const float* __restrict__ img,
                          const float* __restrict__ filt,
                          float* __restrict__ out)
{
    __shared__ __align__(16) __half s_tile[SH][SWH];

    const int tx  = threadIdx.x;             // 0..15
    const int ty  = threadIdx.y;             // 0..15
    const int tid = ty * BDX + tx;

    const int x0 = blockIdx.x * TILE_X;
    const int y0 = blockIdx.y * TILE_Y;
    const size_t plane = (size_t)blockIdx.z * (size_t)(WIDTH * HEIGHT);
    const float* __restrict__ p = img + plane;
    float* __restrict__ o       = out + plane;

    // negated filter, broadcast into half2 registers (kept live; used 8x each)
    __half2 nf2[25];
    #pragma unroll
    for (int j = 0; j < 25; ++j)
        nf2[j] = __half2half2(__float2half(-filt[j]));

    // ---- stage tile into fp16 smem ----
    // smem row r holds gmem row y0-2+r, cols [x0-6, x0+137]
    const bool fast = (x0 >= 8) && (x0 + SWH - 6 <= WIDTH) &&
                      (y0 >= 2) && (y0 + SH - 2 <= HEIGHT);
    if (fast) {
        const float2* __restrict__ g =
            reinterpret_cast<const float2*>(p + (size_t)(y0 - 2) * WIDTH + (x0 - 6));
        #pragma unroll 5
        for (int q = tid; q < SH * (SWH / 2); q += NTHR) {
            int r  = q / (SWH / 2);
            int c2 = q - r * (SWH / 2);
            float2 v = g[(size_t)r * (WIDTH / 2) + c2];
            *reinterpret_cast<__half2*>(&s_tile[r][c2 * 2]) = __floats2half2_rn(v.x, v.y);
        }
    } else {
        for (int q = tid; q < SH * SWH; q += NTHR) {
            int r  = q / SWH;
            int c  = q - r * SWH;
            int gy = y0 - 2 + r;
            int gx = x0 - 6 + c;
            float v = FINF;
            if (gy >= 0 && gy < HEIGHT && gx >= 0 && gx < WIDTH)
                v = p[(size_t)gy * WIDTH + gx];
            s_tile[r][c] = __float2half(v);
        }
    }
    __syncthreads();

    // ---- compute RY x RX outputs per thread (half2-packed columns) ----
    // outputs: rows y0+ty*4+r (r=0..3), cols x0+tx*8+c (c=0..7)
    // candidate halfs live at local L = tx*8+4 .. tx*8+15, inside the
    // 16B-aligned window [tx*8, tx*8+15] -> 2x LDS.128 per smem row.
    __half2 acc[RY][RX / 2];
    const int srow0 = ty * RY;

    #pragma unroll
    for (int i = 0; i < RY + 4; ++i) {
        const uint4* rowp =
            reinterpret_cast<const uint4*>(&s_tile[srow0 + i][tx * 8]);
        uint4 A = rowp[0], B = rowp[1];
        uint32_t W[8] = { A.x, A.y, A.z, A.w, B.x, B.y, B.z, B.w };

        // ps[t] = half2 pair starting at local offset L = tx*8+4+t, t=0..10
        // even t: aligned word; odd t: PRMT splice of adjacent words
        uint32_t psu[11];
        psu[0]  = W[2];  psu[2] = W[3];  psu[4] = W[4];
        psu[6]  = W[5];  psu[8] = W[6];  psu[10] = W[7];
        psu[1]  = __byte_perm(W[2], W[3], 0x5432);
        psu[3]  = __byte_perm(W[3], W[4], 0x5432);
        psu[5]  = __byte_perm(W[4], W[5], 0x5432);
        psu[7]  = __byte_perm(W[5], W[6], 0x5432);
        psu[9]  = __byte_perm(W[6], W[7], 0x5432);

        #pragma unroll
        for (int r = 0; r < RY; ++r) {
            const int fi = i - r;            // filter row hitting output row r
            if (fi < 0 || fi > 4) continue;  // compile-time DCE
            #pragma unroll
            for (int pp = 0; pp < RX / 2; ++pp) {
                #pragma unroll
                for (int fc = 0; fc < 5; ++fc) {
                    // pair for outputs (2pp, 2pp+1), tap (fi, fc): t = 2pp+fc
                    __half2 cand = __hadd2(u2h2(psu[2 * pp + fc]), nf2[fi * 5 + fc]);
                    if (fi == 0 && fc == 0) acc[r][pp] = cand;       // first touch
                    else                    acc[r][pp] = __hmin2(acc[r][pp], cand);
                }
            }
        }
    }

    // ---- store: half2 -> fp32, two float4 per row ----
    const int oy = y0 + ty * RY;
    const int ox = x0 + tx * RX;
    #pragma unroll
    for (int r = 0; r < RY; ++r) {
        float2 f0 = __half22float2(acc[r][0]);
        float2 f1 = __half22float2(acc[r][1]);
        float2 f2 = __half22float2(acc[r][2]);
        float2 f3 = __half22float2(acc[r][3]);
        float* op = o + (size_t)(oy + r) * WIDTH + ox;
        reinterpret_cast<float4*>(op)[0] = make_float4(f0.x, f0.y, f1.x, f1.y);
        reinterpret_cast<float4*>(op)[1] = make_float4(f2.x, f2.y, f3.x, f3.y);
    }
}

extern "C" void kernel_launch(void* const* d_in, const int* in_sizes, int n_in,
                              void* d_out, int out_size)
{
    const float* img  = (const float*)d_in[0];
    const float* filt = (const float*)d_in[1];
    float* out        = (float*)d_out;

    const int planes = in_sizes[0] / (WIDTH * HEIGHT);   // 32*3 = 96

    dim3 block(BDX, BDY);
    dim3 grid(WIDTH / TILE_X, HEIGHT / TILE_Y, planes);
    erosion5x5_h2_kernel<<<grid, block>>>(img, filt, out);
}